// round 1
// baseline (speedup 1.0000x reference)
#include <cuda_runtime.h>
#include <math.h>

#define BB 16
#define L_TOTAL 327
#define S_DIM 256
#define Z_DIM 64
#define S_IN 21
#define PE_DIM 64

// Region layout: idx 0 = collapse token; regions 1..7 follow.
// starts:  1, 25, 41, 89, 193, 209, 313  (lens 24,16,48,104,16,104,14) -> 327 total
__device__ __forceinline__ int reg_of(int i) {
    if (i == 0)  return 0;
    if (i < 25)  return 1;   // cdr3
    if (i < 41)  return 2;   // pep
    if (i < 89)  return 3;   // mhc
    if (i < 193) return 4;   // hv
    if (i < 209) return 5;   // hj
    if (i < 313) return 6;   // lv
    return 7;                // lj
}

__device__ __forceinline__ int pair_id(int i, int j) {
    int ri = reg_of(i), rj = reg_of(j);
    int p = 0;
    if (i == 0 || j == 0) p = 1;
    if (i == 0 && j == 0) p = 0;
    bool cb = (ri == 1) && (rj == 1);
    int d = (i > j) ? (i - j) : (j - i);
    if (cb && d == 1) p = 2;
    if (cb && i != j && d != 1) p = 3;
    if ((ri == 1 && rj >= 2) || (ri >= 2 && rj == 1)) p = 4;
    if (ri >= 2 && ri == rj) p = 5 + (ri - 2);
    if (ri >= 2 && rj >= 2 && ri != rj) {
        int a = (ri < rj ? ri : rj) - 2;
        int b = (ri > rj ? ri : rj) - 2;
        p = 11 + a * (11 - a) / 2 + (b - a - 1);
    }
    return (p < 31) ? p : 31;
}

// ---------------- s kernel: one block per (b, l) token, 256 threads ----------------
__global__ void __launch_bounds__(256)
s_kernel(const float* __restrict__ s0, const float* __restrict__ s1,
         const float* __restrict__ s2, const float* __restrict__ s3,
         const float* __restrict__ s4, const float* __restrict__ s5,
         const float* __restrict__ s6,
         const float* __restrict__ seq_W, const float* __restrict__ seq_b,
         const float* __restrict__ pos_W, const float* __restrict__ pos_b,
         const float* __restrict__ collapse_token,
         const float* __restrict__ collapse_weight,
         const float* __restrict__ region_w,
         float* __restrict__ out)
{
    const int bl = blockIdx.x;           // b * L_TOTAL + l
    const int l  = bl % L_TOTAL;
    const int b  = bl / L_TOTAL;
    const int c  = threadIdx.x;          // output channel 0..255
    float* orow = out + (size_t)bl * S_DIM;

    if (l == 0) {
        orow[c] = collapse_weight[0] * collapse_token[c];
        return;
    }

    __shared__ float srow[S_IN];
    __shared__ float perow[PE_DIM];

    const int k = reg_of(l) - 1;         // region index 0..6
    const int starts[7] = {1, 25, 41, 89, 193, 209, 313};
    const int lens[7]   = {24, 16, 48, 104, 16, 104, 14};
    const int pos = l - starts[k];

    const float* seqp;
    switch (k) {
        case 0: seqp = s0; break;
        case 1: seqp = s1; break;
        case 2: seqp = s2; break;
        case 3: seqp = s3; break;
        case 4: seqp = s4; break;
        case 5: seqp = s5; break;
        default: seqp = s6; break;
    }

    if (c < S_IN)
        srow[c] = seqp[((size_t)b * lens[k] + pos) * S_IN + c];
    if (c >= 32 && c < 32 + PE_DIM) {
        int e = c - 32;
        // angle = pos / 10000^(e/64); exact enough in double for the exponent
        double scale = pow(10000.0, (double)e / (double)PE_DIM);
        float ang = (float)((double)pos / scale);
        perow[e] = (e & 1) ? cosf(ang) : sinf(ang);
    }
    __syncthreads();

    float se = seq_b[c];
    const float* wrow = seq_W + c * S_IN;
    #pragma unroll
    for (int d = 0; d < S_IN; d++) se = fmaf(srow[d], wrow[d], se);

    float pe = pos_b[c];
    const float* prow = pos_W + c * PE_DIM;
    #pragma unroll
    for (int e = 0; e < PE_DIM; e++) pe = fmaf(perow[e], prow[e], pe);

    orow[c] = region_w[k * 2] * se + region_w[k * 2 + 1] * pe;
}

// ---------------- z kernel: one block per (b, i) row, 256 threads ----------------
// z[b,i,j,:] = table[p(i,j)], table has 32 rows x 64 f32 = 8 KB in smem.
// Each block streams 327*64 f32 = 83.7 KB of contiguous float4 stores.
__global__ void __launch_bounds__(256)
z_kernel(const float* __restrict__ pair1_W, const float* __restrict__ pair1_b,
         const float* __restrict__ pair2_W, const float* __restrict__ pair2_b,
         float* __restrict__ zout)
{
    __shared__ float4 table[32 * 16];              // [p][quad] -> 4 floats
    __shared__ unsigned char prow[L_TOTAL];

    const int bl  = blockIdx.x;                    // b * L_TOTAL + i
    const int i   = bl % L_TOTAL;
    const int tid = threadIdx.x;

    // Build the 32x64 table. t1[k][c] = pair1_W[c*8+k] + pair1_b[c] (c<32)
    //                        t2[k][c] = pair2_W[c*4+k] + pair2_b[c] (c<32)
    // table[p][c]    = t1[p/4][c]           for c in [0,32)
    // table[p][32+c] = t2[p%4][c]           for c in [0,32)
    float* ts = (float*)table;
    for (int idx = tid; idx < 32 * 64; idx += 256) {
        int p = idx >> 6;
        int c = idx & 63;
        float v;
        if (c < 32) v = pair1_W[c * 8 + (p >> 2)] + pair1_b[c];
        else { int c2 = c - 32; v = pair2_W[c2 * 4 + (p & 3)] + pair2_b[c2]; }
        ts[idx] = v;
    }
    for (int j = tid; j < L_TOTAL; j += 256)
        prow[j] = (unsigned char)pair_id(i, j);
    __syncthreads();

    float4* zrow = (float4*)zout + (size_t)bl * (L_TOTAL * (Z_DIM / 4));
    const int total = L_TOTAL * (Z_DIM / 4);       // 5232 float4 per row
    for (int v = tid; v < total; v += 256) {
        int j = v >> 4;                            // Z_DIM/4 == 16 quads per j
        zrow[v] = table[((int)prow[j] << 4) + (v & 15)];
    }
}

extern "C" void kernel_launch(void* const* d_in, const int* in_sizes, int n_in,
                              void* d_out, int out_size)
{
    (void)in_sizes; (void)n_in; (void)out_size;
    // Input order (metadata): 0..6 region seqs, 7 seq_W, 8 seq_b, 9 pos_W, 10 pos_b,
    // 11 pair1_W, 12 pair1_b, 13 pair2_W, 14 pair2_b, 15 collapse_token,
    // 16 collapse_weight, 17 region_w, 18..24 masks (unused by reference).
    float* out = (float*)d_out;
    float* zout = out + (size_t)BB * L_TOTAL * S_DIM;   // z follows s

    s_kernel<<<BB * L_TOTAL, 256>>>(
        (const float*)d_in[0], (const float*)d_in[1], (const float*)d_in[2],
        (const float*)d_in[3], (const float*)d_in[4], (const float*)d_in[5],
        (const float*)d_in[6],
        (const float*)d_in[7], (const float*)d_in[8],
        (const float*)d_in[9], (const float*)d_in[10],
        (const float*)d_in[15], (const float*)d_in[16],
        (const float*)d_in[17],
        out);

    z_kernel<<<BB * L_TOTAL, 256>>>(
        (const float*)d_in[11], (const float*)d_in[12],
        (const float*)d_in[13], (const float*)d_in[14],
        zout);
}

// round 2
// speedup vs baseline: 4.2711x; 4.2711x over previous
#include <cuda_runtime.h>
#include <math.h>

#define BB 16
#define L_TOTAL 327
#define S_DIM 256
#define Z_DIM 64
#define S_IN 21
#define PE_DIM 64
#define NTOK (BB * L_TOTAL)

__constant__ int c_starts[7] = {1, 25, 41, 89, 193, 209, 313};
__constant__ int c_lens[7]   = {24, 16, 48, 104, 16, 104, 14};

// Region layout: idx 0 = collapse token; regions 1..7 follow.
__device__ __forceinline__ int reg_of(int i) {
    if (i == 0)  return 0;
    if (i < 25)  return 1;   // cdr3
    if (i < 41)  return 2;   // pep
    if (i < 89)  return 3;   // mhc
    if (i < 193) return 4;   // hv
    if (i < 209) return 5;   // hj
    if (i < 313) return 6;   // lv
    return 7;                // lj
}

__device__ __forceinline__ int pair_id(int i, int j) {
    int ri = reg_of(i), rj = reg_of(j);
    int p = 0;
    if (i == 0 || j == 0) p = 1;
    if (i == 0 && j == 0) p = 0;
    bool cb = (ri == 1) && (rj == 1);
    int d = (i > j) ? (i - j) : (j - i);
    if (cb && d == 1) p = 2;
    if (cb && i != j && d != 1) p = 3;
    if ((ri == 1 && rj >= 2) || (ri >= 2 && rj == 1)) p = 4;
    if (ri >= 2 && ri == rj) p = 5 + (ri - 2);
    if (ri >= 2 && rj >= 2 && ri != rj) {
        int a = (ri < rj ? ri : rj) - 2;
        int b = (ri > rj ? ri : rj) - 2;
        p = 11 + a * (11 - a) / 2 + (b - a - 1);
    }
    return (p < 31) ? p : 31;
}

// ---------------- s kernel v2: persistent blocks, weights in registers ----------------
// Each thread owns output channel c; its 21 seq weights + 64 pos weights stay in
// registers for the whole kernel. Per token: srow/perow staged in smem, broadcast LDS.
__global__ void __launch_bounds__(256, 2)
s_kernel(const float* __restrict__ s0, const float* __restrict__ s1,
         const float* __restrict__ s2, const float* __restrict__ s3,
         const float* __restrict__ s4, const float* __restrict__ s5,
         const float* __restrict__ s6,
         const float* __restrict__ seq_W, const float* __restrict__ seq_b,
         const float* __restrict__ pos_W, const float* __restrict__ pos_b,
         const float* __restrict__ collapse_token,
         const float* __restrict__ collapse_weight,
         const float* __restrict__ region_w,
         float* __restrict__ out)
{
    const int c = threadIdx.x;

    __shared__ float  srow[24];
    __shared__ float4 perow4[16];           // 64 floats as 16 float4
    __shared__ float  inv_scale[64];
    __shared__ float  rw[14];

    // Per-thread register-resident weights
    float sw[S_IN];
    #pragma unroll
    for (int d = 0; d < S_IN; d++) sw[d] = seq_W[c * S_IN + d];
    float4 pw4[16];
    const float4* pwsrc = (const float4*)(pos_W + c * PE_DIM);
    #pragma unroll
    for (int q = 0; q < 16; q++) pw4[q] = pwsrc[q];
    const float sb = seq_b[c];
    const float pb = pos_b[c];
    const float ct = collapse_weight[0] * collapse_token[c];

    if (c < 14) rw[c] = region_w[c];
    if (c < PE_DIM) {
        // 10000^(-e/64) = exp2(-e/64 * log2(10000))
        inv_scale[c] = exp2f(-(float)c * (13.287712379549449f / 64.0f));
    }
    __syncthreads();

    for (int t = blockIdx.x; t < NTOK; t += gridDim.x) {
        const int l = t % L_TOTAL;
        const int b = t / L_TOTAL;
        float* orow = out + (size_t)t * S_DIM;

        if (l == 0) {                       // uniform across block: safe
            orow[c] = ct;
            continue;
        }

        const int k   = reg_of(l) - 1;
        const int pos = l - c_starts[k];

        const float* seqp;
        switch (k) {
            case 0: seqp = s0; break;
            case 1: seqp = s1; break;
            case 2: seqp = s2; break;
            case 3: seqp = s3; break;
            case 4: seqp = s4; break;
            case 5: seqp = s5; break;
            default: seqp = s6; break;
        }

        if (c < S_IN)
            srow[c] = seqp[((size_t)b * c_lens[k] + pos) * S_IN + c];
        if (c >= 64 && c < 64 + PE_DIM) {
            int e = c - 64;
            float ang = (float)pos * inv_scale[e];
            ((float*)perow4)[e] = (e & 1) ? cosf(ang) : sinf(ang);
        }
        __syncthreads();

        float se = sb;
        #pragma unroll
        for (int d = 0; d < S_IN; d++) se = fmaf(srow[d], sw[d], se);

        float pe = pb;
        #pragma unroll
        for (int q = 0; q < 16; q++) {
            float4 p4 = perow4[q];
            pe = fmaf(p4.x, pw4[q].x, pe);
            pe = fmaf(p4.y, pw4[q].y, pe);
            pe = fmaf(p4.z, pw4[q].z, pe);
            pe = fmaf(p4.w, pw4[q].w, pe);
        }

        orow[c] = rw[2 * k] * se + rw[2 * k + 1] * pe;
        __syncthreads();                    // protect srow/perow before next iter
    }
}

// ---------------- z kernel: one block per (b, i) row, 256 threads ----------------
// z[b,i,j,:] = table[p(i,j)], table 32x64 f32 = 8 KB in smem.
// Streaming stores: output is never re-read, hint L2 to evict-first.
__global__ void __launch_bounds__(256)
z_kernel(const float* __restrict__ pair1_W, const float* __restrict__ pair1_b,
         const float* __restrict__ pair2_W, const float* __restrict__ pair2_b,
         float* __restrict__ zout)
{
    __shared__ float4 table[32 * 16];
    __shared__ unsigned char prow[L_TOTAL];

    const int bl  = blockIdx.x;                    // b * L_TOTAL + i
    const int i   = bl % L_TOTAL;
    const int tid = threadIdx.x;

    float* ts = (float*)table;
    for (int idx = tid; idx < 32 * 64; idx += 256) {
        int p = idx >> 6;
        int cc = idx & 63;
        float v;
        if (cc < 32) v = pair1_W[cc * 8 + (p >> 2)] + pair1_b[cc];
        else { int c2 = cc - 32; v = pair2_W[c2 * 4 + (p & 3)] + pair2_b[c2]; }
        ts[idx] = v;
    }
    for (int j = tid; j < L_TOTAL; j += 256)
        prow[j] = (unsigned char)pair_id(i, j);
    __syncthreads();

    float4* zrow = (float4*)zout + (size_t)bl * (L_TOTAL * (Z_DIM / 4));
    const int total = L_TOTAL * (Z_DIM / 4);       // 5232 float4 per row
    for (int v = tid; v < total; v += 256) {
        int j = v >> 4;
        __stcs(&zrow[v], table[((int)prow[j] << 4) + (v & 15)]);
    }
}

extern "C" void kernel_launch(void* const* d_in, const int* in_sizes, int n_in,
                              void* d_out, int out_size)
{
    (void)in_sizes; (void)n_in; (void)out_size;
    float* out  = (float*)d_out;
    float* zout = out + (size_t)BB * L_TOTAL * S_DIM;   // z follows s

    z_kernel<<<BB * L_TOTAL, 256>>>(
        (const float*)d_in[11], (const float*)d_in[12],
        (const float*)d_in[13], (const float*)d_in[14],
        zout);

    s_kernel<<<296, 256>>>(
        (const float*)d_in[0], (const float*)d_in[1], (const float*)d_in[2],
        (const float*)d_in[3], (const float*)d_in[4], (const float*)d_in[5],
        (const float*)d_in[6],
        (const float*)d_in[7], (const float*)d_in[8],
        (const float*)d_in[9], (const float*)d_in[10],
        (const float*)d_in[15], (const float*)d_in[16],
        (const float*)d_in[17],
        out);
}

// round 3
// speedup vs baseline: 5.2157x; 1.2212x over previous
#include <cuda_runtime.h>
#include <math.h>

#define BB 16
#define L_TOTAL 327
#define S_DIM 256
#define Z_DIM 64
#define S_IN 21
#define PE_DIM 64
#define MAXPOS 104

__constant__ int c_starts[7] = {1, 25, 41, 89, 193, 209, 313};
__constant__ int c_lens[7]   = {24, 16, 48, 104, 16, 104, 14};

// Scratch: positional-encoding projection table pe[pos][c], pos < 104, c < 256
__device__ float g_pe[MAXPOS * S_DIM];

// Region layout: idx 0 = collapse token; regions 1..7 follow.
__device__ __forceinline__ int reg_of(int i) {
    if (i == 0)  return 0;
    if (i < 25)  return 1;   // cdr3
    if (i < 41)  return 2;   // pep
    if (i < 89)  return 3;   // mhc
    if (i < 193) return 4;   // hv
    if (i < 209) return 5;   // hj
    if (i < 313) return 6;   // lv
    return 7;                // lj
}

__device__ __forceinline__ int pair_id(int i, int j) {
    int ri = reg_of(i), rj = reg_of(j);
    int p = 0;
    if (i == 0 || j == 0) p = 1;
    if (i == 0 && j == 0) p = 0;
    bool cb = (ri == 1) && (rj == 1);
    int d = (i > j) ? (i - j) : (j - i);
    if (cb && d == 1) p = 2;
    if (cb && i != j && d != 1) p = 3;
    if ((ri == 1 && rj >= 2) || (ri >= 2 && rj == 1)) p = 4;
    if (ri >= 2 && ri == rj) p = 5 + (ri - 2);
    if (ri >= 2 && rj >= 2 && ri != rj) {
        int a = (ri < rj ? ri : rj) - 2;
        int b = (ri > rj ? ri : rj) - 2;
        p = 11 + a * (11 - a) / 2 + (b - a - 1);
    }
    return (p < 31) ? p : 31;
}

// ---------------- PE table kernel: pe[pos][c] = posenc(pos) . pos_W[c] + pos_b[c] ----
__global__ void __launch_bounds__(256)
pe_kernel(const float* __restrict__ pos_W, const float* __restrict__ pos_b)
{
    __shared__ float4 perow4[PE_DIM / 4];
    const int pos = blockIdx.x;
    const int c   = threadIdx.x;

    if (c < PE_DIM) {
        // 10000^(-e/64) = exp2(-e * log2(10000)/64)
        float inv = exp2f(-(float)c * (13.287712379549449f / 64.0f));
        float ang = (float)pos * inv;
        ((float*)perow4)[c] = (c & 1) ? cosf(ang) : sinf(ang);
    }
    __syncthreads();

    float pe = pos_b[c];
    const float4* pw = (const float4*)(pos_W + c * PE_DIM);
    float pe1 = 0.f;
    #pragma unroll
    for (int q = 0; q < 16; q += 2) {
        float4 w0 = pw[q],   p0 = perow4[q];
        float4 w1 = pw[q+1], p1 = perow4[q+1];
        pe  = fmaf(p0.x, w0.x, pe);  pe  = fmaf(p0.y, w0.y, pe);
        pe  = fmaf(p0.z, w0.z, pe);  pe  = fmaf(p0.w, w0.w, pe);
        pe1 = fmaf(p1.x, w1.x, pe1); pe1 = fmaf(p1.y, w1.y, pe1);
        pe1 = fmaf(p1.z, w1.z, pe1); pe1 = fmaf(p1.w, w1.w, pe1);
    }
    g_pe[pos * S_DIM + c] = pe + pe1;
}

// ---------------- fused kernel: one block per (b, i); writes s row + z row ----------
__global__ void __launch_bounds__(256)
fused_kernel(const float* __restrict__ s0, const float* __restrict__ s1,
             const float* __restrict__ s2, const float* __restrict__ s3,
             const float* __restrict__ s4, const float* __restrict__ s5,
             const float* __restrict__ s6,
             const float* __restrict__ seq_W, const float* __restrict__ seq_b,
             const float* __restrict__ collapse_token,
             const float* __restrict__ collapse_weight,
             const float* __restrict__ region_w,
             const float* __restrict__ pair1_W, const float* __restrict__ pair1_b,
             const float* __restrict__ pair2_W, const float* __restrict__ pair2_b,
             float* __restrict__ sout, float* __restrict__ zout)
{
    __shared__ float4 table[32 * 16];              // 32 pair types x 64 f32
    __shared__ unsigned char prow[L_TOTAL];
    __shared__ float srow[24];

    const int bl = blockIdx.x;                     // b * L_TOTAL + i
    const int i  = bl % L_TOTAL;
    const int b  = bl / L_TOTAL;
    const int c  = threadIdx.x;

    // Build the 32x64 z table: [p][0:32)=pair1_W[:,p/4]+b1, [p][32:64)=pair2_W[:,p%4]+b2
    float* ts = (float*)table;
    for (int idx = c; idx < 32 * 64; idx += 256) {
        int p  = idx >> 6;
        int cc = idx & 63;
        float v;
        if (cc < 32) v = pair1_W[cc * 8 + (p >> 2)] + pair1_b[cc];
        else { int c2 = cc - 32; v = pair2_W[c2 * 4 + (p & 3)] + pair2_b[c2]; }
        ts[idx] = v;
    }
    for (int j = c; j < L_TOTAL; j += 256)
        prow[j] = (unsigned char)pair_id(i, j);

    int k = 0, pos = 0;
    if (i > 0) {
        k   = reg_of(i) - 1;
        pos = i - c_starts[k];
        const float* seqp;
        switch (k) {
            case 0: seqp = s0; break;
            case 1: seqp = s1; break;
            case 2: seqp = s2; break;
            case 3: seqp = s3; break;
            case 4: seqp = s4; break;
            case 5: seqp = s5; break;
            default: seqp = s6; break;
        }
        if (c < S_IN)
            srow[c] = seqp[((size_t)b * c_lens[k] + pos) * S_IN + c];
    }
    __syncthreads();

    // ---- s row for this (b, i) token ----
    float* orow = sout + (size_t)bl * S_DIM;
    if (i == 0) {
        orow[c] = collapse_weight[0] * collapse_token[c];
    } else {
        float se = seq_b[c];
        const float* w = seq_W + c * S_IN;
        #pragma unroll
        for (int d = 0; d < S_IN; d++) se = fmaf(srow[d], w[d], se);
        float pe = g_pe[pos * S_DIM + c];
        orow[c] = region_w[2 * k] * se + region_w[2 * k + 1] * pe;
    }

    // ---- z row: stream 327*16 float4 stores ----
    float4* zrow = (float4*)zout + (size_t)bl * (L_TOTAL * (Z_DIM / 4));
    const int total = L_TOTAL * (Z_DIM / 4);       // 5232
    for (int v = c; v < total; v += 256) {
        int j = v >> 4;
        __stcs(&zrow[v], table[((int)prow[j] << 4) + (v & 15)]);
    }
}

extern "C" void kernel_launch(void* const* d_in, const int* in_sizes, int n_in,
                              void* d_out, int out_size)
{
    (void)in_sizes; (void)n_in; (void)out_size;
    // 0..6 region seqs, 7 seq_W, 8 seq_b, 9 pos_W, 10 pos_b, 11 pair1_W, 12 pair1_b,
    // 13 pair2_W, 14 pair2_b, 15 collapse_token, 16 collapse_weight, 17 region_w,
    // 18..24 masks (unused)
    float* out  = (float*)d_out;
    float* zout = out + (size_t)BB * L_TOTAL * S_DIM;   // z follows s

    pe_kernel<<<MAXPOS, 256>>>((const float*)d_in[9], (const float*)d_in[10]);

    fused_kernel<<<BB * L_TOTAL, 256>>>(
        (const float*)d_in[0], (const float*)d_in[1], (const float*)d_in[2],
        (const float*)d_in[3], (const float*)d_in[4], (const float*)d_in[5],
        (const float*)d_in[6],
        (const float*)d_in[7], (const float*)d_in[8],
        (const float*)d_in[15], (const float*)d_in[16],
        (const float*)d_in[17],
        (const float*)d_in[11], (const float*)d_in[12],
        (const float*)d_in[13], (const float*)d_in[14],
        out, zout);
}